// round 1
// baseline (speedup 1.0000x reference)
#include <cuda_runtime.h>

#define NREL 3
#define DDIM 64
#define N_ITEMS 100000
#define N_ITEMS_P1 100001
#define BATCH 8192
#define LSEQ 100

// Scratch accumulators (zeroed every launch by zero_kernel).
__device__ float g_Gii[NREL * DDIM * DDIM];
__device__ float g_Gui[NREL * DDIM * DDIM];
__device__ float g_pos[NREL];

// ---------------------------------------------------------------------------
__global__ void zero_kernel() {
    int i = blockIdx.x * blockDim.x + threadIdx.x;
    const int n = NREL * DDIM * DDIM;
    if (i < n) { g_Gii[i] = 0.f; g_Gui[i] = 0.f; }
    if (i < NREL) g_pos[i] = 0.f;
}

// ---------------------------------------------------------------------------
// Shared gram accumulation: 256 threads as 16x16 tile grid, each thread owns a
// 4x4 sub-tile of the 64x64 gram per relation. Only tx >= ty (upper-triangle
// tiles) are computed — the final kernel weights off-diagonal by 2.
__device__ __forceinline__ void gram_accum_tile(const float* __restrict__ tile,
                                                float acc[NREL][4][4],
                                                int ty, int tx) {
    for (int s = 0; s < 32; s++) {
        const float* row = tile + s * 192;
#pragma unroll
        for (int r = 0; r < NREL; r++) {
            float4 av = *(const float4*)(row + r * 64 + ty * 4);
            float4 bv = *(const float4*)(row + r * 64 + tx * 4);
            float a[4] = {av.x, av.y, av.z, av.w};
            float b[4] = {bv.x, bv.y, bv.z, bv.w};
#pragma unroll
            for (int i = 0; i < 4; i++)
#pragma unroll
                for (int j = 0; j < 4; j++)
                    acc[r][i][j] += a[i] * b[j];
        }
    }
}

// ---------------------------------------------------------------------------
// One fused kernel; role decided by blockIdx so the FFMA-bound gram work and
// the L2-bound pos-gather work co-schedule on the SMs.
//   bid % 9 == 0 : gram role. aux = bid/9 in [0,384): aux<320 -> item gram,
//                  else user gram (aux-320 in [0,64)).
//   bid % 9 != 0 : pos role. p = (bid/9)*8 + (bid%9-1) in [0,3072);
//                  rel = p/1024, 8 users per block (one per warp).
__global__ __launch_bounds__(256) void main_kernel(
    const int* __restrict__ input_u,
    const int* __restrict__ lab0,
    const int* __restrict__ lab1,
    const int* __restrict__ lab2,
    const float* __restrict__ ua,
    const float* __restrict__ ia,
    const float* __restrict__ r0,
    const float* __restrict__ r1,
    const float* __restrict__ r2)
{
    const int bid = blockIdx.x;
    const int tid = threadIdx.x;
    const int role = bid % 9;

    if (role == 0) {
        __shared__ float tile[32 * 192];   // 32 rows x (3 rel x 64) floats
        const int aux = bid / 9;           // 0..383
        const int ty = tid >> 4, tx = tid & 15;
        const bool active = (tx >= ty);

        float acc[NREL][4][4];
#pragma unroll
        for (int r = 0; r < NREL; r++)
#pragma unroll
            for (int i = 0; i < 4; i++)
#pragma unroll
                for (int j = 0; j < 4; j++) acc[r][i][j] = 0.f;

        if (aux < 320) {
            // ---- item gram: stream ia (coalesced), tiles of 32 items ----
            const float4* src4 = (const float4*)ia;
            float4* t4 = (float4*)tile;
            const int n_tiles = (N_ITEMS_P1 + 31) / 32;   // 3126
            for (int t = aux; t < n_tiles; t += 320) {
                const int base = t * 32;
                __syncthreads();
                for (int q = tid; q < 32 * 48; q += 256) {
                    int s = q / 48, f = q % 48;
                    int item = base + s;
                    float4 v = make_float4(0.f, 0.f, 0.f, 0.f);
                    if (item < N_ITEMS_P1) v = src4[item * 48 + f];
                    t4[q] = v;
                }
                __syncthreads();
                if (active) gram_accum_tile(tile, acc, ty, tx);
            }
            if (active) {
#pragma unroll
                for (int r = 0; r < NREL; r++)
#pragma unroll
                    for (int i = 0; i < 4; i++)
#pragma unroll
                        for (int j = 0; j < 4; j++)
                            atomicAdd(&g_Gii[r * 4096 + (ty * 4 + i) * 64 + tx * 4 + j],
                                      acc[r][i][j]);
            }
        } else {
            // ---- user gram: gather ua rows by input_u ----
            const int ub = aux - 320;      // 0..63
            const float4* src4 = (const float4*)ua;
            float4* t4 = (float4*)tile;
            for (int t = ub; t < BATCH / 32; t += 64) {   // 256 tiles
                const int base = t * 32;
                __syncthreads();
                for (int q = tid; q < 32 * 48; q += 256) {
                    int s = q / 48, f = q % 48;
                    int u = input_u[base + s];
                    t4[q] = src4[u * 48 + f];
                }
                __syncthreads();
                if (active) gram_accum_tile(tile, acc, ty, tx);
            }
            if (active) {
#pragma unroll
                for (int r = 0; r < NREL; r++)
#pragma unroll
                    for (int i = 0; i < 4; i++)
#pragma unroll
                        for (int j = 0; j < 4; j++)
                            atomicAdd(&g_Gui[r * 4096 + (ty * 4 + i) * 64 + tx * 4 + j],
                                      acc[r][i][j]);
            }
        }
    } else {
        // ---- pos role: one warp per (user, rel), 8 users/block, uniform rel ----
        const int p = (bid / 9) * 8 + (role - 1);   // 0..3071
        const int warp = tid >> 5, lane = tid & 31;
        const int rel = p >> 10;                    // p / 1024
        const int user = ((p & 1023) << 3) + warp;  // 0..8191

        const int* lab = (rel == 0 ? lab0 : rel == 1 ? lab1 : lab2) + user * LSEQ;
        const float* rr = (rel == 0 ? r0 : rel == 1 ? r1 : r2);

        const int u = input_u[user];
        float2 w2 = *(const float2*)(ua + u * 192 + rel * 64 + lane * 2);
        float2 rv = *(const float2*)(rr + lane * 2);
        const float wx = w2.x * rv.x;
        const float wy = w2.y * rv.y;
        const float* iab = ia + rel * 64 + lane * 2;

        float acc = 0.f;
        const float c1 = 1.0f - 0.1f;               // 1 - WID
#pragma unroll 5
        for (int l0 = 0; l0 < LSEQ; l0 += 4) {
            int4 la = *(const int4*)(lab + l0);
            float2 v0 = *(const float2*)(iab + la.x * 192);
            float2 v1 = *(const float2*)(iab + la.y * 192);
            float2 v2 = *(const float2*)(iab + la.z * 192);
            float2 v3 = *(const float2*)(iab + la.w * 192);
            float p0 = v0.x * wx + v0.y * wy;
            float p1 = v1.x * wx + v1.y * wy;
            float p2 = v2.x * wx + v2.y * wy;
            float p3 = v3.x * wx + v3.y * wy;
#pragma unroll
            for (int off = 16; off > 0; off >>= 1) {
                p0 += __shfl_xor_sync(0xffffffffu, p0, off);
                p1 += __shfl_xor_sync(0xffffffffu, p1, off);
                p2 += __shfl_xor_sync(0xffffffffu, p2, off);
                p3 += __shfl_xor_sync(0xffffffffu, p3, off);
            }
            if (lane == 0) {
                if (la.x != N_ITEMS) acc += c1 * p0 * p0 - 2.f * p0;
                if (la.y != N_ITEMS) acc += c1 * p1 * p1 - 2.f * p1;
                if (la.z != N_ITEMS) acc += c1 * p2 * p2 - 2.f * p2;
                if (la.w != N_ITEMS) acc += c1 * p3 * p3 - 2.f * p3;
            }
        }
        __shared__ float wsum[8];
        if (lane == 0) wsum[warp] = acc;
        __syncthreads();
        if (tid == 0) {
            float s = 0.f;
#pragma unroll
            for (int w = 0; w < 8; w++) s += wsum[w];
            atomicAdd(&g_pos[rel], s);
        }
    }
}

// ---------------------------------------------------------------------------
// Combine: loss = sum_i COEF[i]*(WID*sum_{b<=c} m*Gii*Gui*r_b*r_c + pos_i)
//          emb_loss = DECAY*0.5*(trace(Gui)+trace(Gii)) summed over rels.
__global__ void final_kernel(const float* __restrict__ r0,
                             const float* __restrict__ r1,
                             const float* __restrict__ r2,
                             float* __restrict__ out, int out_size)
{
    __shared__ float s1[256], s2[256];
    const int tid = threadIdx.x;
    const float coef[3] = {0.16666f, 0.66666f, 0.16666f};

    float lsum = 0.f, tsum = 0.f;
    for (int idx = tid; idx < NREL * DDIM * DDIM; idx += 256) {
        int rel = idx >> 12;
        int rem = idx & 4095;
        int b = rem >> 6, c = rem & 63;
        if (b > c) continue;                      // only upper triangle is valid
        float gii = g_Gii[idx];
        float gui = g_Gui[idx];
        if (b == c) tsum += gii + gui;
        const float* rr = (rel == 0 ? r0 : rel == 1 ? r1 : r2);
        float m = (b == c) ? 1.f : 2.f;
        lsum += coef[rel] * 0.1f * m * gii * gui * rr[b] * rr[c];
    }
    s1[tid] = lsum;
    s2[tid] = tsum;
    __syncthreads();
    for (int s = 128; s > 0; s >>= 1) {
        if (tid < s) { s1[tid] += s1[tid + s]; s2[tid] += s2[tid + s]; }
        __syncthreads();
    }
    if (tid == 0) {
        float loss = s1[0];
#pragma unroll
        for (int r = 0; r < NREL; r++) loss += coef[r] * g_pos[r];
        out[0] = loss;
        if (out_size > 1) out[1] = 0.01f * 0.5f * s2[0];   // DECAY * regularizer
    }
}

// ---------------------------------------------------------------------------
extern "C" void kernel_launch(void* const* d_in, const int* in_sizes, int n_in,
                              void* d_out, int out_size) {
    const int* input_u = (const int*)d_in[0];
    const int* lab0 = (const int*)d_in[1];
    const int* lab1 = (const int*)d_in[2];
    const int* lab2 = (const int*)d_in[3];
    const float* ua = (const float*)d_in[4];
    const float* ia = (const float*)d_in[5];
    const float* r0 = (const float*)d_in[6];
    const float* r1 = (const float*)d_in[7];
    const float* r2 = (const float*)d_in[8];

    zero_kernel<<<48, 256>>>();
    main_kernel<<<3456, 256>>>(input_u, lab0, lab1, lab2, ua, ia, r0, r1, r2);
    final_kernel<<<1, 256>>>(r0, r1, r2, (float*)d_out, out_size);
}

// round 2
// speedup vs baseline: 1.2058x; 1.2058x over previous
#include <cuda_runtime.h>

#define NREL 3
#define DDIM 64
#define N_ITEMS 100000
#define N_ITEMS_P1 100001
#define BATCH 8192
#define LSEQ 100

// Scratch accumulators (zeroed every launch by zero_kernel).
__device__ float g_Gii[NREL * DDIM * DDIM];
__device__ float g_Gui[NREL * DDIM * DDIM];
__device__ float g_pos[NREL];

// ---------------------------------------------------------------------------
__global__ void zero_kernel() {
    int i = blockIdx.x * blockDim.x + threadIdx.x;
    const int n = NREL * DDIM * DDIM;
    if (i < n) { g_Gii[i] = 0.f; g_Gui[i] = 0.f; }
    if (i < NREL) g_pos[i] = 0.f;
}

// ---------------------------------------------------------------------------
// Shared gram accumulation: 256 threads as 16x16 tile grid, each thread owns a
// 4x4 sub-tile of the 64x64 gram per relation. Only tx >= ty (upper-triangle
// tiles) are computed — the final kernel weights off-diagonal by 2.
__device__ __forceinline__ void gram_accum_tile(const float* __restrict__ tile,
                                                float acc[NREL][4][4],
                                                int ty, int tx) {
    for (int s = 0; s < 32; s++) {
        const float* row = tile + s * 192;
#pragma unroll
        for (int r = 0; r < NREL; r++) {
            float4 av = *(const float4*)(row + r * 64 + ty * 4);
            float4 bv = *(const float4*)(row + r * 64 + tx * 4);
            float a[4] = {av.x, av.y, av.z, av.w};
            float b[4] = {bv.x, bv.y, bv.z, bv.w};
#pragma unroll
            for (int i = 0; i < 4; i++)
#pragma unroll
                for (int j = 0; j < 4; j++)
                    acc[r][i][j] += a[i] * b[j];
        }
    }
}

// ---------------------------------------------------------------------------
// One fused kernel; role decided by blockIdx so the FFMA-bound gram work and
// the L2-bound pos-gather work co-schedule on the SMs.
//   bid % 9 == 0 : gram role. aux = bid/9 in [0,384): aux<320 -> item gram,
//                  else user gram (aux-320 in [0,64)).
//   bid % 9 != 0 : pos role. p = (bid/9)*8 + (bid%9-1) in [0,3072);
//                  rel = p/1024, 8 users per block (one per warp).
__global__ __launch_bounds__(256) void main_kernel(
    const int* __restrict__ input_u,
    const int* __restrict__ lab0,
    const int* __restrict__ lab1,
    const int* __restrict__ lab2,
    const float* __restrict__ ua,
    const float* __restrict__ ia,
    const float* __restrict__ r0,
    const float* __restrict__ r1,
    const float* __restrict__ r2)
{
    const int bid = blockIdx.x;
    const int tid = threadIdx.x;
    const int role = bid % 9;

    if (role == 0) {
        __shared__ float tile[32 * 192];   // 32 rows x (3 rel x 64) floats
        const int aux = bid / 9;           // 0..383
        const int ty = tid >> 4, tx = tid & 15;
        const bool active = (tx >= ty);

        float acc[NREL][4][4];
#pragma unroll
        for (int r = 0; r < NREL; r++)
#pragma unroll
            for (int i = 0; i < 4; i++)
#pragma unroll
                for (int j = 0; j < 4; j++) acc[r][i][j] = 0.f;

        if (aux < 320) {
            // ---- item gram: stream ia (coalesced), tiles of 32 items ----
            const float4* src4 = (const float4*)ia;
            float4* t4 = (float4*)tile;
            const int n_tiles = (N_ITEMS_P1 + 31) / 32;   // 3126
            for (int t = aux; t < n_tiles; t += 320) {
                const int base = t * 32;
                __syncthreads();
                for (int q = tid; q < 32 * 48; q += 256) {
                    int s = q / 48, f = q % 48;
                    int item = base + s;
                    float4 v = make_float4(0.f, 0.f, 0.f, 0.f);
                    if (item < N_ITEMS_P1) v = src4[item * 48 + f];
                    t4[q] = v;
                }
                __syncthreads();
                if (active) gram_accum_tile(tile, acc, ty, tx);
            }
            if (active) {
#pragma unroll
                for (int r = 0; r < NREL; r++)
#pragma unroll
                    for (int i = 0; i < 4; i++)
#pragma unroll
                        for (int j = 0; j < 4; j++)
                            atomicAdd(&g_Gii[r * 4096 + (ty * 4 + i) * 64 + tx * 4 + j],
                                      acc[r][i][j]);
            }
        } else {
            // ---- user gram: gather ua rows by input_u ----
            const int ub = aux - 320;      // 0..63
            const float4* src4 = (const float4*)ua;
            float4* t4 = (float4*)tile;
            for (int t = ub; t < BATCH / 32; t += 64) {   // 256 tiles
                const int base = t * 32;
                __syncthreads();
                for (int q = tid; q < 32 * 48; q += 256) {
                    int s = q / 48, f = q % 48;
                    int u = input_u[base + s];
                    t4[q] = src4[u * 48 + f];
                }
                __syncthreads();
                if (active) gram_accum_tile(tile, acc, ty, tx);
            }
            if (active) {
#pragma unroll
                for (int r = 0; r < NREL; r++)
#pragma unroll
                    for (int i = 0; i < 4; i++)
#pragma unroll
                        for (int j = 0; j < 4; j++)
                            atomicAdd(&g_Gui[r * 4096 + (ty * 4 + i) * 64 + tx * 4 + j],
                                      acc[r][i][j]);
            }
        }
    } else {
        // ---- pos role: one warp per (user, rel), 8 users/block ----
        // Two item rows per LDG.128: lanes 0-15 fetch label 2k (float4 each),
        // lanes 16-31 fetch label 2k+1. Reduction = halving butterfly within
        // each 16-lane group: 15 shuffles per 32 labels (vs 5 per label).
        const int p = (bid / 9) * 8 + (role - 1);   // 0..3071
        const int warp = tid >> 5, lane = tid & 31;
        const int rel = p >> 10;                    // p / 1024
        const int user = ((p & 1023) << 3) + warp;  // 0..8191

        const int* lab = (rel == 0 ? lab0 : rel == 1 ? lab1 : lab2) + user * LSEQ;
        const float* rr = (rel == 0 ? r0 : rel == 1 ? r1 : r2);

        const int half = lane >> 4;     // which label of the pair
        const int qd = lane & 15;       // quarter-dim index within the row

        const int u = input_u[user];
        float4 w4 = *(const float4*)(ua + u * 192 + rel * 64 + qd * 4);
        float4 r4 = *(const float4*)(rr + qd * 4);
        w4.x *= r4.x; w4.y *= r4.y; w4.z *= r4.z; w4.w *= r4.w;
        const float4* iab = (const float4*)ia + rel * 16 + qd;  // row stride 48 float4

        float acc = 0.f;
        const float c1 = 1.0f - 0.1f;               // 1 - WID
        const unsigned FULL = 0xffffffffu;

#pragma unroll
        for (int b = 0; b < 3; b++) {
            const int base = b * 32;
            int4 la[8];
#pragma unroll
            for (int j = 0; j < 8; j++) la[j] = *(const int4*)(lab + base + j * 4);

            float pv[16];
#pragma unroll
            for (int k = 0; k < 16; k++) {
                int l0 = (k & 1) ? la[k >> 1].z : la[k >> 1].x;  // label base+2k
                int l1 = (k & 1) ? la[k >> 1].w : la[k >> 1].y;  // label base+2k+1
                int row = half ? l1 : l0;
                float4 v = iab[row * 48];
                pv[k] = v.x * w4.x + v.y * w4.y + v.z * w4.z + v.w * w4.w;
            }
            // halving butterfly: 16 values over each 16-lane group
#pragma unroll
            for (int st = 0; st < 4; st++) {
                const int o = 8 >> st;
                const bool up = (qd & o) != 0;
#pragma unroll
                for (int i = 0; i < (8 >> st); i++) {
                    float give = up ? pv[i] : pv[i + o];
                    float got = __shfl_xor_sync(FULL, give, o);
                    pv[i] = (up ? pv[i + o] : pv[i]) + got;
                }
            }
            // lane (16*half + qd) now holds full dot for label base + 2*qd + half
            float v = pv[0];
            int ml = lab[base + 2 * qd + half];
            if (ml != N_ITEMS) acc += c1 * v * v - 2.f * v;
        }

        // tail: labels 96..99 via two paired LDG.128
        {
            int4 lt = *(const int4*)(lab + 96);     // {l96,l97,l98,l99}
            int rowA = half ? lt.y : lt.x;
            int rowB = half ? lt.w : lt.z;
            float4 vA = iab[rowA * 48];
            float4 vB = iab[rowB * 48];
            float pA = vA.x * w4.x + vA.y * w4.y + vA.z * w4.z + vA.w * w4.w;
            float pB = vB.x * w4.x + vB.y * w4.y + vB.z * w4.z + vB.w * w4.w;
#pragma unroll
            for (int o = 8; o >= 1; o >>= 1) {
                pA += __shfl_xor_sync(FULL, pA, o);
                pB += __shfl_xor_sync(FULL, pB, o);
            }
            // every lane of each half-group holds that half's total
            if (qd == 0) {
                int mA = half ? lt.y : lt.x;        // label 96+half
                int mB = half ? lt.w : lt.z;        // label 98+half
                if (mA != N_ITEMS) acc += c1 * pA * pA - 2.f * pA;
                if (mB != N_ITEMS) acc += c1 * pB * pB - 2.f * pB;
            }
        }

        // reduce acc across warp, then block, one atomic per block
#pragma unroll
        for (int o = 16; o >= 1; o >>= 1)
            acc += __shfl_xor_sync(FULL, acc, o);

        __shared__ float wsum[8];
        if (lane == 0) wsum[warp] = acc;
        __syncthreads();
        if (tid == 0) {
            float s = 0.f;
#pragma unroll
            for (int w = 0; w < 8; w++) s += wsum[w];
            atomicAdd(&g_pos[rel], s);
        }
    }
}

// ---------------------------------------------------------------------------
// Combine: loss = sum_i COEF[i]*(WID*sum_{b<=c} m*Gii*Gui*r_b*r_c + pos_i)
//          emb_loss = DECAY*0.5*(trace(Gui)+trace(Gii)) summed over rels.
__global__ void final_kernel(const float* __restrict__ r0,
                             const float* __restrict__ r1,
                             const float* __restrict__ r2,
                             float* __restrict__ out, int out_size)
{
    __shared__ float s1[256], s2[256];
    const int tid = threadIdx.x;
    const float coef[3] = {0.16666f, 0.66666f, 0.16666f};

    float lsum = 0.f, tsum = 0.f;
    for (int idx = tid; idx < NREL * DDIM * DDIM; idx += 256) {
        int rel = idx >> 12;
        int rem = idx & 4095;
        int b = rem >> 6, c = rem & 63;
        if (b > c) continue;                      // only upper triangle is valid
        float gii = g_Gii[idx];
        float gui = g_Gui[idx];
        if (b == c) tsum += gii + gui;
        const float* rr = (rel == 0 ? r0 : rel == 1 ? r1 : r2);
        float m = (b == c) ? 1.f : 2.f;
        lsum += coef[rel] * 0.1f * m * gii * gui * rr[b] * rr[c];
    }
    s1[tid] = lsum;
    s2[tid] = tsum;
    __syncthreads();
    for (int s = 128; s > 0; s >>= 1) {
        if (tid < s) { s1[tid] += s1[tid + s]; s2[tid] += s2[tid + s]; }
        __syncthreads();
    }
    if (tid == 0) {
        float loss = s1[0];
#pragma unroll
        for (int r = 0; r < NREL; r++) loss += coef[r] * g_pos[r];
        out[0] = loss;
        if (out_size > 1) out[1] = 0.01f * 0.5f * s2[0];   // DECAY * regularizer
    }
}

// ---------------------------------------------------------------------------
extern "C" void kernel_launch(void* const* d_in, const int* in_sizes, int n_in,
                              void* d_out, int out_size) {
    const int* input_u = (const int*)d_in[0];
    const int* lab0 = (const int*)d_in[1];
    const int* lab1 = (const int*)d_in[2];
    const int* lab2 = (const int*)d_in[3];
    const float* ua = (const float*)d_in[4];
    const float* ia = (const float*)d_in[5];
    const float* r0 = (const float*)d_in[6];
    const float* r1 = (const float*)d_in[7];
    const float* r2 = (const float*)d_in[8];

    zero_kernel<<<48, 256>>>();
    main_kernel<<<3456, 256>>>(input_u, lab0, lab1, lab2, ua, ia, r0, r1, r2);
    final_kernel<<<1, 256>>>(r0, r1, r2, (float*)d_out, out_size);
}

// round 5
// speedup vs baseline: 1.5811x; 1.3113x over previous
#include <cuda_runtime.h>
#include <cstdint>

#define NREL 3
#define N_ITEMS 100000
#define N_ITEMS_P1 100001
#define BATCH 8192
#define LSEQ 100

#define NG_ITEM 148
#define NG_USER 128
#define NPOS 3072
#define POS_BASE (NG_ITEM + NG_USER)
#define GRID_TOTAL (NG_ITEM + NG_USER + NPOS)

// staging: 32 items x 200 floats (stride 200 -> conflict-free frag loads)
#define STG_STRIDE 200
#define DYN_BYTES (32 * STG_STRIDE * 4)   // 25600 B < 48KB default limit

__device__ float g_Gii[NREL * 4096];
__device__ float g_Gui[NREL * 4096];
__device__ float g_pos[NREL];

// Kept gram tiles per rel: (mt, nt) with nt >= 2*mt  (covers all b<=c)
__constant__ unsigned char c_mt[20] = {0,0,0,0,0,0,0,0, 1,1,1,1,1,1, 2,2,2,2, 3,3};
__constant__ unsigned char c_nt[20] = {0,1,2,3,4,5,6,7, 2,3,4,5,6,7, 4,5,6,7, 6,7};

// ---------------------------------------------------------------------------
__global__ void zero_kernel() {
    int i = blockIdx.x * blockDim.x + threadIdx.x;
    const int n = NREL * 4096;
    if (i < n) { g_Gii[i] = 0.f; g_Gui[i] = 0.f; }
    if (i < NREL) g_pos[i] = 0.f;
}

// m16n8k8 tf32 mma, C += A*B (row.col)
__device__ __forceinline__ void mma_tf32(float c[4], uint32_t a0, uint32_t a1,
                                         uint32_t a2, uint32_t a3,
                                         uint32_t b0, uint32_t b1) {
    asm volatile(
        "mma.sync.aligned.m16n8k8.row.col.f32.tf32.tf32.f32 "
        "{%0,%1,%2,%3}, {%4,%5,%6,%7}, {%8,%9}, {%0,%1,%2,%3};"
        : "+f"(c[0]), "+f"(c[1]), "+f"(c[2]), "+f"(c[3])
        : "r"(a0), "r"(a1), "r"(a2), "r"(a3), "r"(b0), "r"(b1));
}

// ---------------------------------------------------------------------------
__global__ __launch_bounds__(256) void main_kernel(
    const int* __restrict__ input_u,
    const int* __restrict__ lab0,
    const int* __restrict__ lab1,
    const int* __restrict__ lab2,
    const float* __restrict__ ua,
    const float* __restrict__ ia,
    const float* __restrict__ r0,
    const float* __restrict__ r1,
    const float* __restrict__ r2)
{
    extern __shared__ __align__(16) float dynsm[];
    const int bid = blockIdx.x;
    const int tid = threadIdx.x;
    const int wid = tid >> 5, lane = tid & 31;

    __shared__ float wsum[8];

    if (bid < NG_ITEM) {
        // ============ item gram via mma.sync tf32 (tensor pipe) ============
        float* stg = dynsm;                        // [32][200]
        const int gid = lane >> 2;                 // 0..7
        const int tig = lane & 3;                  // 0..3

        // warp's tile slice of the 60 kept tiles
        const int t_beg = (wid * 60) >> 3;
        const int t_end = ((wid + 1) * 60) >> 3;
        const int t_cnt = t_end - t_beg;           // 7 or 8

        int abase[8], bbase[8], obase[8];
#pragma unroll
        for (int t = 0; t < 8; t++) {
            int g = t_beg + t;
            if (t < t_cnt) {
                int rel = g / 20, q = g % 20;
                int mt = c_mt[q], nt = c_nt[q];
                abase[t] = rel * 64 + mt * 16;     // dim base for A (rows)
                bbase[t] = rel * 64 + nt * 8;      // dim base for B (cols)
                obase[t] = rel * 4096 + mt * 16 * 64 + nt * 8;
            } else { abase[t] = bbase[t] = obase[t] = 0; }
        }

        float c[8][4];
#pragma unroll
        for (int t = 0; t < 8; t++)
#pragma unroll
            for (int i = 0; i < 4; i++) c[t][i] = 0.f;

        const float4* src4 = (const float4*)ia;
        const int NCH = (N_ITEMS_P1 + 31) / 32;    // 3126
        for (int ch = bid; ch < NCH; ch += NG_ITEM) {
            const int base = ch * 32;
            __syncthreads();                        // readers of prev chunk done
            for (int q = tid; q < 32 * 48; q += 256) {
                int s = q / 48, f = q % 48;
                int item = base + s;
                float4 v = make_float4(0.f, 0.f, 0.f, 0.f);
                if (item < N_ITEMS_P1) v = src4[item * 48 + f];
                *(float4*)(stg + s * STG_STRIDE + f * 4) = v;
            }
            __syncthreads();

            // frag row pointers: rows (8k+tig) and (8k+tig+4)
            const float* rp0 = stg + tig * STG_STRIDE;
            const float* rp4 = stg + (tig + 4) * STG_STRIDE;
#pragma unroll
            for (int k = 0; k < 4; k++) {
                const float* q0 = rp0 + k * 8 * STG_STRIDE;
                const float* q4 = rp4 + k * 8 * STG_STRIDE;
#pragma unroll
                for (int t = 0; t < 8; t++) {
                    if (t < t_cnt) {
                        uint32_t a0 = __float_as_uint(q0[abase[t] + gid]);
                        uint32_t a1 = __float_as_uint(q0[abase[t] + gid + 8]);
                        uint32_t a2 = __float_as_uint(q4[abase[t] + gid]);
                        uint32_t a3 = __float_as_uint(q4[abase[t] + gid + 8]);
                        uint32_t b0 = __float_as_uint(q0[bbase[t] + gid]);
                        uint32_t b1 = __float_as_uint(q4[bbase[t] + gid]);
                        mma_tf32(c[t], a0, a1, a2, a3, b0, b1);
                    }
                }
            }
        }

        // write out: c0:(gid, 2tig) c1:(gid, 2tig+1) c2:(gid+8, 2tig) c3:(gid+8, 2tig+1)
#pragma unroll
        for (int t = 0; t < 8; t++) {
            if (t < t_cnt) {
                int r0i = obase[t] + gid * 64 + tig * 2;
                int r1i = obase[t] + (gid + 8) * 64 + tig * 2;
                atomicAdd(&g_Gii[r0i],     c[t][0]);
                atomicAdd(&g_Gii[r0i + 1], c[t][1]);
                atomicAdd(&g_Gii[r1i],     c[t][2]);
                atomicAdd(&g_Gii[r1i + 1], c[t][3]);
            }
        }

    } else if (bid < POS_BASE) {
        // ============ user gram (CUDA cores, full matrix) ============
        float* tile = dynsm;                       // 32 x 192 floats
        const int ub = bid - NG_ITEM;              // 0..127
        const int ty = tid >> 4, tx = tid & 15;

        float acc[NREL][4][4];
#pragma unroll
        for (int rl = 0; rl < NREL; rl++)
#pragma unroll
            for (int i = 0; i < 4; i++)
#pragma unroll
                for (int j = 0; j < 4; j++) acc[rl][i][j] = 0.f;

        const float4* src4 = (const float4*)ua;
        float4* t4 = (float4*)tile;
        for (int t = ub; t < BATCH / 32; t += NG_USER) {
            const int base = t * 32;
            __syncthreads();
            for (int q = tid; q < 32 * 48; q += 256) {
                int s = q / 48, f = q % 48;
                int u = input_u[base + s];
                t4[q] = src4[u * 48 + f];
            }
            __syncthreads();
            for (int s = 0; s < 32; s++) {
                const float* row = tile + s * 192;
#pragma unroll
                for (int rl = 0; rl < NREL; rl++) {
                    float4 av = *(const float4*)(row + rl * 64 + ty * 4);
                    float4 bv = *(const float4*)(row + rl * 64 + tx * 4);
                    float a[4] = {av.x, av.y, av.z, av.w};
                    float b[4] = {bv.x, bv.y, bv.z, bv.w};
#pragma unroll
                    for (int i = 0; i < 4; i++)
#pragma unroll
                        for (int j = 0; j < 4; j++)
                            acc[rl][i][j] += a[i] * b[j];
                }
            }
        }
#pragma unroll
        for (int rl = 0; rl < NREL; rl++)
#pragma unroll
            for (int i = 0; i < 4; i++)
#pragma unroll
                for (int j = 0; j < 4; j++)
                    atomicAdd(&g_Gui[rl * 4096 + (ty * 4 + i) * 64 + tx * 4 + j],
                              acc[rl][i][j]);

    } else {
        // ============ pos role (R2-proven) ============
        const int p = bid - POS_BASE;              // 0..3071
        const int warp = wid;
        const int rel = p >> 10;
        const int user = ((p & 1023) << 3) + warp;

        const int* lab = (rel == 0 ? lab0 : rel == 1 ? lab1 : lab2) + user * LSEQ;
        const float* rr = (rel == 0 ? r0 : rel == 1 ? r1 : r2);

        const int half = lane >> 4;
        const int qd = lane & 15;

        const int u = input_u[user];
        float4 w4 = *(const float4*)(ua + u * 192 + rel * 64 + qd * 4);
        float4 r4 = *(const float4*)(rr + qd * 4);
        w4.x *= r4.x; w4.y *= r4.y; w4.z *= r4.z; w4.w *= r4.w;
        const float4* iab = (const float4*)ia + rel * 16 + qd;

        float acc = 0.f;
        const float c1 = 1.0f - 0.1f;
        const unsigned FULL = 0xffffffffu;

#pragma unroll
        for (int b = 0; b < 3; b++) {
            const int base = b * 32;
            int4 la[8];
#pragma unroll
            for (int j = 0; j < 8; j++) la[j] = *(const int4*)(lab + base + j * 4);

            float pv[16];
#pragma unroll
            for (int k = 0; k < 16; k++) {
                int l0 = (k & 1) ? la[k >> 1].z : la[k >> 1].x;
                int l1 = (k & 1) ? la[k >> 1].w : la[k >> 1].y;
                int row = half ? l1 : l0;
                float4 v = iab[row * 48];
                pv[k] = v.x * w4.x + v.y * w4.y + v.z * w4.z + v.w * w4.w;
            }
#pragma unroll
            for (int st = 0; st < 4; st++) {
                const int o = 8 >> st;
                const bool up = (qd & o) != 0;
#pragma unroll
                for (int i = 0; i < (8 >> st); i++) {
                    float give = up ? pv[i] : pv[i + o];
                    float got = __shfl_xor_sync(FULL, give, o);
                    pv[i] = (up ? pv[i + o] : pv[i]) + got;
                }
            }
            float v = pv[0];
            int ml = lab[base + 2 * qd + half];
            if (ml != N_ITEMS) acc += c1 * v * v - 2.f * v;
        }
        {
            int4 lt = *(const int4*)(lab + 96);
            int rowA = half ? lt.y : lt.x;
            int rowB = half ? lt.w : lt.z;
            float4 vA = iab[rowA * 48];
            float4 vB = iab[rowB * 48];
            float pA = vA.x * w4.x + vA.y * w4.y + vA.z * w4.z + vA.w * w4.w;
            float pB = vB.x * w4.x + vB.y * w4.y + vB.z * w4.z + vB.w * w4.w;
#pragma unroll
            for (int o = 8; o >= 1; o >>= 1) {
                pA += __shfl_xor_sync(FULL, pA, o);
                pB += __shfl_xor_sync(FULL, pB, o);
            }
            if (qd == 0) {
                int mA = half ? lt.y : lt.x;
                int mB = half ? lt.w : lt.z;
                if (mA != N_ITEMS) acc += c1 * pA * pA - 2.f * pA;
                if (mB != N_ITEMS) acc += c1 * pB * pB - 2.f * pB;
            }
        }
#pragma unroll
        for (int o = 16; o >= 1; o >>= 1)
            acc += __shfl_xor_sync(FULL, acc, o);

        if (lane == 0) wsum[warp] = acc;
        __syncthreads();
        if (tid == 0) {
            float s = 0.f;
#pragma unroll
            for (int w = 0; w < 8; w++) s += wsum[w];
            atomicAdd(&g_pos[rel], s);
        }
    }
}

// ---------------------------------------------------------------------------
// Gii holds only b<=c (upper); Gui is full. Off-diagonal weighted x2.
__global__ void final_kernel(const float* __restrict__ r0,
                             const float* __restrict__ r1,
                             const float* __restrict__ r2,
                             float* __restrict__ out, int out_size)
{
    __shared__ float s1[256], s2[256];
    const int tid = threadIdx.x;
    const float coef[3] = {0.16666f, 0.66666f, 0.16666f};

    float lsum = 0.f, tsum = 0.f;
    for (int idx = tid; idx < NREL * 4096; idx += 256) {
        int rel = idx >> 12;
        int rem = idx & 4095;
        int b = rem >> 6, c = rem & 63;
        if (b > c) continue;
        float gii = g_Gii[idx];
        float gui = g_Gui[idx];
        if (b == c) tsum += gii + gui;
        const float* rr = (rel == 0 ? r0 : rel == 1 ? r1 : r2);
        float m = (b == c) ? 1.f : 2.f;
        lsum += coef[rel] * 0.1f * m * gii * gui * rr[b] * rr[c];
    }
    s1[tid] = lsum;
    s2[tid] = tsum;
    __syncthreads();
    for (int s = 128; s > 0; s >>= 1) {
        if (tid < s) { s1[tid] += s1[tid + s]; s2[tid] += s2[tid + s]; }
        __syncthreads();
    }
    if (tid == 0) {
        float loss = s1[0];
#pragma unroll
        for (int r = 0; r < NREL; r++) loss += coef[r] * g_pos[r];
        out[0] = loss;
        if (out_size > 1) out[1] = 0.01f * 0.5f * s2[0];
    }
}

// ---------------------------------------------------------------------------
extern "C" void kernel_launch(void* const* d_in, const int* in_sizes, int n_in,
                              void* d_out, int out_size) {
    const int* input_u = (const int*)d_in[0];
    const int* lab0 = (const int*)d_in[1];
    const int* lab1 = (const int*)d_in[2];
    const int* lab2 = (const int*)d_in[3];
    const float* ua = (const float*)d_in[4];
    const float* ia = (const float*)d_in[5];
    const float* r0 = (const float*)d_in[6];
    const float* r1 = (const float*)d_in[7];
    const float* r2 = (const float*)d_in[8];

    zero_kernel<<<48, 256>>>();
    main_kernel<<<GRID_TOTAL, 256, DYN_BYTES>>>(input_u, lab0, lab1, lab2,
                                                ua, ia, r0, r1, r2);
    final_kernel<<<1, 256>>>(r0, r1, r2, (float*)d_out, out_size);
}

// round 6
// speedup vs baseline: 1.9790x; 1.2516x over previous
#include <cuda_runtime.h>
#include <cstdint>

#define NREL 3
#define N_ITEMS 100000
#define N_ITEMS_P1 100001
#define BATCH 8192
#define LSEQ 100

#define NG_ITEM 148
#define NG_USER 128
#define NPOS 3072
#define GRID_TOTAL 3352          // 280 specials (bid%12==0) + 3072 pos

#define STG_STRIDE 200           // floats per staged item row (conflict-free)
#define STG_FLOATS (32 * STG_STRIDE)
#define DYN_BYTES (2 * STG_FLOATS * 4)   // 51200 B, double-buffered

__device__ float g_Gii[NREL * 4096];   // zero at module load; final_kernel re-zeros
__device__ float g_Gui[NREL * 4096];
__device__ float g_pos[NREL];

// ---------------------------------------------------------------------------
__device__ __forceinline__ uint32_t smem_u32(const void* p) {
    uint32_t a;
    asm("{ .reg .u64 t; cvta.to.shared.u64 t, %1; cvt.u32.u64 %0, t; }"
        : "=r"(a) : "l"(p));
    return a;
}

__device__ __forceinline__ uint32_t tf32r(float x) {     // round-to-nearest tf32
    uint32_t r;
    asm("cvt.rna.tf32.f32 %0, %1;" : "=r"(r) : "f"(x));
    return r;
}

// m16n8k8 tf32 mma, C += A*B (row.col)
__device__ __forceinline__ void mma_tf32(float c[4], uint32_t a0, uint32_t a1,
                                         uint32_t a2, uint32_t a3,
                                         uint32_t b0, uint32_t b1) {
    asm volatile(
        "mma.sync.aligned.m16n8k8.row.col.f32.tf32.tf32.f32 "
        "{%0,%1,%2,%3}, {%4,%5,%6,%7}, {%8,%9}, {%0,%1,%2,%3};"
        : "+f"(c[0]), "+f"(c[1]), "+f"(c[2]), "+f"(c[3])
        : "r"(a0), "r"(a1), "r"(a2), "r"(a3), "r"(b0), "r"(b1));
}

// cp.async prefetch of one 32-item chunk into a staging buffer (zfill OOB)
__device__ __forceinline__ void prefetch_chunk(uint32_t stg_u,
                                               const float4* __restrict__ src4,
                                               int base, int tid) {
#pragma unroll
    for (int it = 0; it < 6; it++) {
        int q = tid + it * 256;              // 1536 = 6*256 float4 transfers
        int s = q / 48, f = q % 48;
        int item = base + s;
        int vit = (item < N_ITEMS_P1) ? item : 0;
        const float4* g = src4 + (size_t)vit * 48 + f;
        uint32_t sz = (item < N_ITEMS_P1) ? 16u : 0u;
        uint32_t d = stg_u + (uint32_t)(s * STG_STRIDE + f * 4) * 4u;
        asm volatile("cp.async.cg.shared.global [%0], [%1], 16, %2;"
                     :: "r"(d), "l"(g), "r"(sz) : "memory");
    }
}
#define CP_COMMIT() asm volatile("cp.async.commit_group;" ::: "memory")
#define CP_WAIT1()  asm volatile("cp.async.wait_group 1;" ::: "memory")
#define CP_WAIT0()  asm volatile("cp.async.wait_group 0;" ::: "memory")

// ---------------------------------------------------------------------------
// Accumulate CNT gram tiles (one A-base, nt0..nt0+CNT-1) on one 32-item chunk.
// A fragments loaded once per k-step, reused across the CNT tiles.
template<int CNT, int OFF>
__device__ __forceinline__ void gram_tiles(const float* __restrict__ stg,
                                           float (&c)[8][4],
                                           int abase, int nt0, int gid, int tig) {
    const int rel64 = (abase >> 6) << 6;
    const float* rp0 = stg + tig * STG_STRIDE;
    const float* rp4 = stg + (tig + 4) * STG_STRIDE;
#pragma unroll
    for (int k = 0; k < 4; k++) {
        const float* q0 = rp0 + k * 8 * STG_STRIDE;
        const float* q4 = rp4 + k * 8 * STG_STRIDE;
        uint32_t a0 = tf32r(q0[abase + gid]);
        uint32_t a1 = tf32r(q0[abase + gid + 8]);
        uint32_t a2 = tf32r(q4[abase + gid]);
        uint32_t a3 = tf32r(q4[abase + gid + 8]);
#pragma unroll
        for (int j = 0; j < CNT; j++) {
            const int bb = rel64 + (nt0 + j) * 8;
            uint32_t b0 = tf32r(q0[bb + gid]);
            uint32_t b1 = tf32r(q4[bb + gid]);
            mma_tf32(c[OFF + j], a0, a1, a2, a3, b0, b1);
        }
    }
}

template<int CNT, int OFF>
__device__ __forceinline__ void gram_out(float (&c)[8][4], int abase, int nt0,
                                         int gid, int tig) {
#pragma unroll
    for (int j = 0; j < CNT; j++) {
        int ob = abase * 64 + (nt0 + j) * 8;          // = rel*4096 + mt*1024 + nt*8
        int i0 = ob + gid * 64 + tig * 2;
        int i1 = ob + (gid + 8) * 64 + tig * 2;
        atomicAdd(&g_Gii[i0],     c[OFF + j][0]);
        atomicAdd(&g_Gii[i0 + 1], c[OFF + j][1]);
        atomicAdd(&g_Gii[i1],     c[OFF + j][2]);
        atomicAdd(&g_Gii[i1 + 1], c[OFF + j][3]);
    }
}

// ---------------------------------------------------------------------------
__global__ __launch_bounds__(256) void main_kernel(
    const int* __restrict__ input_u,
    const int* __restrict__ lab0,
    const int* __restrict__ lab1,
    const int* __restrict__ lab2,
    const float* __restrict__ ua,
    const float* __restrict__ ia,
    const float* __restrict__ r0,
    const float* __restrict__ r1,
    const float* __restrict__ r2)
{
    extern __shared__ __align__(16) float dynsm[];
    const int bid = blockIdx.x;
    const int tid = threadIdx.x;
    const int wid = tid >> 5, lane = tid & 31;

    __shared__ float wsum[8];

    if (bid % 12 == 0) {
        const int sid = bid / 12;            // 0..279
        if (sid < NG_ITEM) {
            // ======== item gram: mma.sync tf32, cp.async double buffer ========
            const int gid = lane >> 2;       // 0..7
            const int tig = lane & 3;        // 0..3
            float* stgA = dynsm;
            float* stgB = dynsm + STG_FLOATS;
            const uint32_t stgA_u = smem_u32(stgA);
            const uint32_t stgB_u = smem_u32(stgB);

            float c[8][4];
#pragma unroll
            for (int t = 0; t < 8; t++)
#pragma unroll
                for (int i = 0; i < 4; i++) c[t][i] = 0.f;

            const float4* src4 = (const float4*)ia;
            const int NCH = (N_ITEMS_P1 + 31) / 32;   // 3126
            int ch = sid;
            prefetch_chunk(stgA_u, src4, ch * 32, tid);
            CP_COMMIT();
            int cur = 0;
            for (; ch < NCH; ch += NG_ITEM) {
                const int nxt = ch + NG_ITEM;
                const bool hn = (nxt < NCH);
                if (hn) prefetch_chunk(cur ? stgA_u : stgB_u, src4, nxt * 32, tid);
                CP_COMMIT();
                if (hn) CP_WAIT1(); else CP_WAIT0();
                __syncthreads();
                const float* sc = cur ? stgB : stgA;
                if (wid < 3) {
                    gram_tiles<8, 0>(sc, c, wid * 64, 0, gid, tig);
                } else if (wid < 6) {
                    gram_tiles<6, 0>(sc, c, (wid - 3) * 64 + 16, 2, gid, tig);
                    gram_tiles<2, 6>(sc, c, (wid - 3) * 64 + 48, 6, gid, tig);
                } else if (wid == 6) {
                    gram_tiles<4, 0>(sc, c, 32, 4, gid, tig);
                    gram_tiles<4, 4>(sc, c, 96, 4, gid, tig);
                } else {
                    gram_tiles<4, 0>(sc, c, 160, 4, gid, tig);
                }
                __syncthreads();
                cur ^= 1;
            }
            if (wid < 3) {
                gram_out<8, 0>(c, wid * 64, 0, gid, tig);
            } else if (wid < 6) {
                gram_out<6, 0>(c, (wid - 3) * 64 + 16, 2, gid, tig);
                gram_out<2, 6>(c, (wid - 3) * 64 + 48, 6, gid, tig);
            } else if (wid == 6) {
                gram_out<4, 0>(c, 32, 4, gid, tig);
                gram_out<4, 4>(c, 96, 4, gid, tig);
            } else {
                gram_out<4, 0>(c, 160, 4, gid, tig);
            }
        } else if (sid < NG_ITEM + NG_USER) {
            // ======== user gram (CUDA cores, full matrix, fp32) ========
            float* tile = dynsm;                       // 32 x 192 floats
            const int ub = sid - NG_ITEM;              // 0..127
            const int ty = tid >> 4, tx = tid & 15;

            float acc[NREL][4][4];
#pragma unroll
            for (int rl = 0; rl < NREL; rl++)
#pragma unroll
                for (int i = 0; i < 4; i++)
#pragma unroll
                    for (int j = 0; j < 4; j++) acc[rl][i][j] = 0.f;

            const float4* src4 = (const float4*)ua;
            float4* t4 = (float4*)tile;
            for (int t = ub; t < BATCH / 32; t += NG_USER) {
                const int base = t * 32;
                __syncthreads();
                for (int q = tid; q < 32 * 48; q += 256) {
                    int s = q / 48, f = q % 48;
                    int u = input_u[base + s];
                    t4[q] = src4[u * 48 + f];
                }
                __syncthreads();
                for (int s = 0; s < 32; s++) {
                    const float* row = tile + s * 192;
#pragma unroll
                    for (int rl = 0; rl < NREL; rl++) {
                        float4 av = *(const float4*)(row + rl * 64 + ty * 4);
                        float4 bv = *(const float4*)(row + rl * 64 + tx * 4);
                        float a[4] = {av.x, av.y, av.z, av.w};
                        float b[4] = {bv.x, bv.y, bv.z, bv.w};
#pragma unroll
                        for (int i = 0; i < 4; i++)
#pragma unroll
                            for (int j = 0; j < 4; j++)
                                acc[rl][i][j] += a[i] * b[j];
                    }
                }
            }
#pragma unroll
            for (int rl = 0; rl < NREL; rl++)
#pragma unroll
                for (int i = 0; i < 4; i++)
#pragma unroll
                    for (int j = 0; j < 4; j++)
                        atomicAdd(&g_Gui[rl * 4096 + (ty * 4 + i) * 64 + tx * 4 + j],
                                  acc[rl][i][j]);
        }
        // else: spare special block, idle
    } else {
        // ======== pos role (R2/R5-proven) ========
        const int p = bid - bid / 12 - 1;          // 0..3071
        const int warp = wid;
        const int rel = p >> 10;
        const int user = ((p & 1023) << 3) + warp;

        const int* lab = (rel == 0 ? lab0 : rel == 1 ? lab1 : lab2) + user * LSEQ;
        const float* rr = (rel == 0 ? r0 : rel == 1 ? r1 : r2);

        const int half = lane >> 4;
        const int qd = lane & 15;

        const int u = input_u[user];
        float4 w4 = *(const float4*)(ua + u * 192 + rel * 64 + qd * 4);
        float4 r4 = *(const float4*)(rr + qd * 4);
        w4.x *= r4.x; w4.y *= r4.y; w4.z *= r4.z; w4.w *= r4.w;
        const float4* iab = (const float4*)ia + rel * 16 + qd;

        float acc = 0.f;
        const float c1 = 1.0f - 0.1f;
        const unsigned FULL = 0xffffffffu;

#pragma unroll
        for (int b = 0; b < 3; b++) {
            const int base = b * 32;
            int4 la[8];
#pragma unroll
            for (int j = 0; j < 8; j++) la[j] = *(const int4*)(lab + base + j * 4);

            float pv[16];
#pragma unroll
            for (int k = 0; k < 16; k++) {
                int l0 = (k & 1) ? la[k >> 1].z : la[k >> 1].x;
                int l1 = (k & 1) ? la[k >> 1].w : la[k >> 1].y;
                int row = half ? l1 : l0;
                float4 v = iab[row * 48];
                pv[k] = v.x * w4.x + v.y * w4.y + v.z * w4.z + v.w * w4.w;
            }
#pragma unroll
            for (int st = 0; st < 4; st++) {
                const int o = 8 >> st;
                const bool up = (qd & o) != 0;
#pragma unroll
                for (int i = 0; i < (8 >> st); i++) {
                    float give = up ? pv[i] : pv[i + o];
                    float got = __shfl_xor_sync(FULL, give, o);
                    pv[i] = (up ? pv[i + o] : pv[i]) + got;
                }
            }
            float v = pv[0];
            int ml = lab[base + 2 * qd + half];
            if (ml != N_ITEMS) acc += c1 * v * v - 2.f * v;
        }
        {
            int4 lt = *(const int4*)(lab + 96);
            int rowA = half ? lt.y : lt.x;
            int rowB = half ? lt.w : lt.z;
            float4 vA = iab[rowA * 48];
            float4 vB = iab[rowB * 48];
            float pA = vA.x * w4.x + vA.y * w4.y + vA.z * w4.z + vA.w * w4.w;
            float pB = vB.x * w4.x + vB.y * w4.y + vB.z * w4.z + vB.w * w4.w;
#pragma unroll
            for (int o = 8; o >= 1; o >>= 1) {
                pA += __shfl_xor_sync(FULL, pA, o);
                pB += __shfl_xor_sync(FULL, pB, o);
            }
            if (qd == 0) {
                int mA = half ? lt.y : lt.x;
                int mB = half ? lt.w : lt.z;
                if (mA != N_ITEMS) acc += c1 * pA * pA - 2.f * pA;
                if (mB != N_ITEMS) acc += c1 * pB * pB - 2.f * pB;
            }
        }
#pragma unroll
        for (int o = 16; o >= 1; o >>= 1)
            acc += __shfl_xor_sync(FULL, acc, o);

        if (lane == 0) wsum[warp] = acc;
        __syncthreads();
        if (tid == 0) {
            float s = 0.f;
#pragma unroll
            for (int w = 0; w < 8; w++) s += wsum[w];
            atomicAdd(&g_pos[rel], s);
        }
    }
}

// ---------------------------------------------------------------------------
// Gii holds only b<=c (upper); Gui is full. Off-diagonal weighted x2.
// Re-zeros all accumulators after reading (graph-replay safe).
__global__ void final_kernel(const float* __restrict__ r0,
                             const float* __restrict__ r1,
                             const float* __restrict__ r2,
                             float* __restrict__ out, int out_size)
{
    __shared__ float s1[256], s2[256];
    const int tid = threadIdx.x;
    const float coef[3] = {0.16666f, 0.66666f, 0.16666f};

    float lsum = 0.f, tsum = 0.f;
    for (int idx = tid; idx < NREL * 4096; idx += 256) {
        float gii = g_Gii[idx];
        float gui = g_Gui[idx];
        g_Gii[idx] = 0.f;
        g_Gui[idx] = 0.f;
        int rel = idx >> 12;
        int rem = idx & 4095;
        int b = rem >> 6, cc = rem & 63;
        if (b <= cc) {
            if (b == cc) tsum += gii + gui;
            const float* rr = (rel == 0 ? r0 : rel == 1 ? r1 : r2);
            float m = (b == cc) ? 1.f : 2.f;
            lsum += coef[rel] * 0.1f * m * gii * gui * rr[b] * rr[cc];
        }
    }
    s1[tid] = lsum;
    s2[tid] = tsum;
    __syncthreads();
    for (int s = 128; s > 0; s >>= 1) {
        if (tid < s) { s1[tid] += s1[tid + s]; s2[tid] += s2[tid + s]; }
        __syncthreads();
    }
    if (tid == 0) {
        float loss = s1[0];
#pragma unroll
        for (int r = 0; r < NREL; r++) { loss += coef[r] * g_pos[r]; g_pos[r] = 0.f; }
        out[0] = loss;
        if (out_size > 1) out[1] = 0.01f * 0.5f * s2[0];
    }
}

__global__ void dummy_kernel() {}

// ---------------------------------------------------------------------------
extern "C" void kernel_launch(void* const* d_in, const int* in_sizes, int n_in,
                              void* d_out, int out_size) {
    const int* input_u = (const int*)d_in[0];
    const int* lab0 = (const int*)d_in[1];
    const int* lab1 = (const int*)d_in[2];
    const int* lab2 = (const int*)d_in[3];
    const float* ua = (const float*)d_in[4];
    const float* ia = (const float*)d_in[5];
    const float* r0 = (const float*)d_in[6];
    const float* r1 = (const float*)d_in[7];
    const float* r2 = (const float*)d_in[8];

    cudaFuncSetAttribute(main_kernel, cudaFuncAttributeMaxDynamicSharedMemorySize,
                         DYN_BYTES);

    main_kernel<<<GRID_TOTAL, 256, DYN_BYTES>>>(input_u, lab0, lab1, lab2,
                                                ua, ia, r0, r1, r2);
    final_kernel<<<1, 256>>>(r0, r1, r2, (float*)d_out, out_size);
    dummy_kernel<<<1, 32>>>();   // pads launch stream so ncu -s 5 lands on main_kernel
}

// round 7
// speedup vs baseline: 2.1394x; 1.0810x over previous
#include <cuda_runtime.h>
#include <cstdint>

#define NREL 3
#define N_ITEMS 100000
#define N_ITEMS_P1 100001
#define BATCH 8192
#define LSEQ 100

#define NG_ITEM 148
#define NG_USER 128
#define NPOS 3072
#define GRID_TOTAL 3352          // 280 specials (bid%12==0) + 3072 pos

#define STG_STRIDE 200           // floats per staged item row (conflict-free)
#define STG_FLOATS (32 * STG_STRIDE)
#define DYN_BYTES (2 * STG_FLOATS * 4)   // 51200 B, double-buffered

__device__ float g_Gii[NREL * 4096];   // zero at module load; final_kernel re-zeros
__device__ float g_Gui[NREL * 4096];
__device__ float g_pos[NREL];

// ---------------------------------------------------------------------------
__device__ __forceinline__ uint32_t smem_u32(const void* p) {
    uint32_t a;
    asm("{ .reg .u64 t; cvta.to.shared.u64 t, %1; cvt.u32.u64 %0, t; }"
        : "=r"(a) : "l"(p));
    return a;
}

__device__ __forceinline__ uint32_t tf32r(float x) {     // round-to-nearest tf32
    uint32_t r;
    asm("cvt.rna.tf32.f32 %0, %1;" : "=r"(r) : "f"(x));
    return r;
}

// m16n8k8 tf32 mma, C += A*B (row.col)
__device__ __forceinline__ void mma_tf32(float c[4], uint32_t a0, uint32_t a1,
                                         uint32_t a2, uint32_t a3,
                                         uint32_t b0, uint32_t b1) {
    asm volatile(
        "mma.sync.aligned.m16n8k8.row.col.f32.tf32.tf32.f32 "
        "{%0,%1,%2,%3}, {%4,%5,%6,%7}, {%8,%9}, {%0,%1,%2,%3};"
        : "+f"(c[0]), "+f"(c[1]), "+f"(c[2]), "+f"(c[3])
        : "r"(a0), "r"(a1), "r"(a2), "r"(a3), "r"(b0), "r"(b1));
}

// cp.async prefetch of one 32-item chunk into a staging buffer (zfill OOB)
__device__ __forceinline__ void prefetch_chunk(uint32_t stg_u,
                                               const float4* __restrict__ src4,
                                               int base, int tid) {
#pragma unroll
    for (int it = 0; it < 6; it++) {
        int q = tid + it * 256;              // 1536 = 6*256 float4 transfers
        int s = q / 48, f = q % 48;
        int item = base + s;
        int vit = (item < N_ITEMS_P1) ? item : 0;
        const float4* g = src4 + (size_t)vit * 48 + f;
        uint32_t sz = (item < N_ITEMS_P1) ? 16u : 0u;
        uint32_t d = stg_u + (uint32_t)(s * STG_STRIDE + f * 4) * 4u;
        asm volatile("cp.async.cg.shared.global [%0], [%1], 16, %2;"
                     :: "r"(d), "l"(g), "r"(sz) : "memory");
    }
}
#define CP_COMMIT() asm volatile("cp.async.commit_group;" ::: "memory")
#define CP_WAIT1()  asm volatile("cp.async.wait_group 1;" ::: "memory")
#define CP_WAIT0()  asm volatile("cp.async.wait_group 0;" ::: "memory")

// ---------------------------------------------------------------------------
// Accumulate CNT gram tiles (one A-base, nt0..nt0+CNT-1) on one 32-item chunk.
template<int CNT, int OFF>
__device__ __forceinline__ void gram_tiles(const float* __restrict__ stg,
                                           float (&c)[8][4],
                                           int abase, int nt0, int gid, int tig) {
    const int rel64 = (abase >> 6) << 6;
    const float* rp0 = stg + tig * STG_STRIDE;
    const float* rp4 = stg + (tig + 4) * STG_STRIDE;
#pragma unroll
    for (int k = 0; k < 4; k++) {
        const float* q0 = rp0 + k * 8 * STG_STRIDE;
        const float* q4 = rp4 + k * 8 * STG_STRIDE;
        uint32_t a0 = tf32r(q0[abase + gid]);
        uint32_t a1 = tf32r(q0[abase + gid + 8]);
        uint32_t a2 = tf32r(q4[abase + gid]);
        uint32_t a3 = tf32r(q4[abase + gid + 8]);
#pragma unroll
        for (int j = 0; j < CNT; j++) {
            const int bb = rel64 + (nt0 + j) * 8;
            uint32_t b0 = tf32r(q0[bb + gid]);
            uint32_t b1 = tf32r(q4[bb + gid]);
            mma_tf32(c[OFF + j], a0, a1, a2, a3, b0, b1);
        }
    }
}

template<int CNT, int OFF>
__device__ __forceinline__ void gram_out(float (&c)[8][4], int abase, int nt0,
                                         int gid, int tig) {
#pragma unroll
    for (int j = 0; j < CNT; j++) {
        int ob = abase * 64 + (nt0 + j) * 8;          // = rel*4096 + mt*1024 + nt*8
        int i0 = ob + gid * 64 + tig * 2;
        int i1 = ob + (gid + 8) * 64 + tig * 2;
        atomicAdd(&g_Gii[i0],     c[OFF + j][0]);
        atomicAdd(&g_Gii[i0 + 1], c[OFF + j][1]);
        atomicAdd(&g_Gii[i1],     c[OFF + j][2]);
        atomicAdd(&g_Gii[i1 + 1], c[OFF + j][3]);
    }
}

// ---------------------------------------------------------------------------
__global__ __launch_bounds__(256, 3) void main_kernel(
    const int* __restrict__ input_u,
    const int* __restrict__ lab0,
    const int* __restrict__ lab1,
    const int* __restrict__ lab2,
    const float* __restrict__ ua,
    const float* __restrict__ ia,
    const float* __restrict__ r0,
    const float* __restrict__ r1,
    const float* __restrict__ r2)
{
    extern __shared__ __align__(16) float dynsm[];
    const int bid = blockIdx.x;
    const int tid = threadIdx.x;
    const int wid = tid >> 5, lane = tid & 31;

    __shared__ float wsum[8];

    if (bid % 12 == 0) {
        const int sid = bid / 12;            // 0..279
        if (sid < NG_ITEM) {
            // ======== item gram: mma.sync tf32, cp.async double buffer ========
            const int gid = lane >> 2;       // 0..7
            const int tig = lane & 3;        // 0..3
            float* stgA = dynsm;
            float* stgB = dynsm + STG_FLOATS;
            const uint32_t stgA_u = smem_u32(stgA);
            const uint32_t stgB_u = smem_u32(stgB);

            float c[8][4];
#pragma unroll
            for (int t = 0; t < 8; t++)
#pragma unroll
                for (int i = 0; i < 4; i++) c[t][i] = 0.f;

            const float4* src4 = (const float4*)ia;
            const int NCH = (N_ITEMS_P1 + 31) / 32;   // 3126
            int ch = sid;
            prefetch_chunk(stgA_u, src4, ch * 32, tid);
            CP_COMMIT();
            int cur = 0;
            for (; ch < NCH; ch += NG_ITEM) {
                const int nxt = ch + NG_ITEM;
                const bool hn = (nxt < NCH);
                if (hn) prefetch_chunk(cur ? stgA_u : stgB_u, src4, nxt * 32, tid);
                CP_COMMIT();
                if (hn) CP_WAIT1(); else CP_WAIT0();
                __syncthreads();
                const float* sc = cur ? stgB : stgA;
                if (wid < 3) {
                    gram_tiles<8, 0>(sc, c, wid * 64, 0, gid, tig);
                } else if (wid < 6) {
                    gram_tiles<6, 0>(sc, c, (wid - 3) * 64 + 16, 2, gid, tig);
                    gram_tiles<2, 6>(sc, c, (wid - 3) * 64 + 48, 6, gid, tig);
                } else if (wid == 6) {
                    gram_tiles<4, 0>(sc, c, 32, 4, gid, tig);
                    gram_tiles<4, 4>(sc, c, 96, 4, gid, tig);
                } else {
                    gram_tiles<4, 0>(sc, c, 160, 4, gid, tig);
                }
                __syncthreads();
                cur ^= 1;
            }
            if (wid < 3) {
                gram_out<8, 0>(c, wid * 64, 0, gid, tig);
            } else if (wid < 6) {
                gram_out<6, 0>(c, (wid - 3) * 64 + 16, 2, gid, tig);
                gram_out<2, 6>(c, (wid - 3) * 64 + 48, 6, gid, tig);
            } else if (wid == 6) {
                gram_out<4, 0>(c, 32, 4, gid, tig);
                gram_out<4, 4>(c, 96, 4, gid, tig);
            } else {
                gram_out<4, 0>(c, 160, 4, gid, tig);
            }
        } else if (sid < NG_ITEM + NG_USER) {
            // ======== user gram (CUDA cores, full matrix, fp32) ========
            float* tile = dynsm;                       // 32 x 192 floats
            const int ub = sid - NG_ITEM;              // 0..127
            const int ty = tid >> 4, tx = tid & 15;

            float acc[NREL][4][4];
#pragma unroll
            for (int rl = 0; rl < NREL; rl++)
#pragma unroll
                for (int i = 0; i < 4; i++)
#pragma unroll
                    for (int j = 0; j < 4; j++) acc[rl][i][j] = 0.f;

            const float4* src4 = (const float4*)ua;
            float4* t4 = (float4*)tile;
            for (int t = ub; t < BATCH / 32; t += NG_USER) {
                const int base = t * 32;
                __syncthreads();
                for (int q = tid; q < 32 * 48; q += 256) {
                    int s = q / 48, f = q % 48;
                    int u = input_u[base + s];
                    t4[q] = src4[u * 48 + f];
                }
                __syncthreads();
                for (int s = 0; s < 32; s++) {
                    const float* row = tile + s * 192;
#pragma unroll
                    for (int rl = 0; rl < NREL; rl++) {
                        float4 av = *(const float4*)(row + rl * 64 + ty * 4);
                        float4 bv = *(const float4*)(row + rl * 64 + tx * 4);
                        float a[4] = {av.x, av.y, av.z, av.w};
                        float b[4] = {bv.x, bv.y, bv.z, bv.w};
#pragma unroll
                        for (int i = 0; i < 4; i++)
#pragma unroll
                            for (int j = 0; j < 4; j++)
                                acc[rl][i][j] += a[i] * b[j];
                    }
                }
            }
#pragma unroll
            for (int rl = 0; rl < NREL; rl++)
#pragma unroll
                for (int i = 0; i < 4; i++)
#pragma unroll
                    for (int j = 0; j < 4; j++)
                        atomicAdd(&g_Gui[rl * 4096 + (ty * 4 + i) * 64 + tx * 4 + j],
                                  acc[rl][i][j]);
        }
        // else: spare special block, idle
    } else {
        // ======== pos role: labels one-per-lane + shfl broadcast ========
        const int p = bid - bid / 12 - 1;          // 0..3071
        const int warp = wid;
        const int rel = p >> 10;
        const int user = ((p & 1023) << 3) + warp;

        const int* lab = (rel == 0 ? lab0 : rel == 1 ? lab1 : lab2) + user * LSEQ;
        const float* rr = (rel == 0 ? r0 : rel == 1 ? r1 : r2);

        const int half = lane >> 4;
        const int qd = lane & 15;

        const int u = input_u[user];
        float4 w4 = *(const float4*)(ua + u * 192 + rel * 64 + qd * 4);
        float4 r4 = *(const float4*)(rr + qd * 4);
        w4.x *= r4.x; w4.y *= r4.y; w4.z *= r4.z; w4.w *= r4.w;
        const float4* iab = (const float4*)ia + rel * 16 + qd;

        float acc = 0.f;
        const float c1 = 1.0f - 0.1f;
        const unsigned FULL = 0xffffffffu;

#pragma unroll
        for (int b = 0; b < 3; b++) {
            const int base = b * 32;
            // one label per lane (coalesced, warp-wide 128B line)
            const int myla = lab[base + lane];

            float pv[16];
#pragma unroll
            for (int k = 0; k < 16; k++) {
                int row = __shfl_sync(FULL, myla, 2 * k + half);
                float4 v = iab[row * 48];
                pv[k] = v.x * w4.x + v.y * w4.y + v.z * w4.z + v.w * w4.w;
            }
#pragma unroll
            for (int st = 0; st < 4; st++) {
                const int o = 8 >> st;
                const bool up = (qd & o) != 0;
#pragma unroll
                for (int i = 0; i < (8 >> st); i++) {
                    float give = up ? pv[i] : pv[i + o];
                    float got = __shfl_xor_sync(FULL, give, o);
                    pv[i] = (up ? pv[i + o] : pv[i]) + got;
                }
            }
            // lane (16*half + qd) holds full dot for label base + 2*qd + half
            float v = pv[0];
            int ml = __shfl_sync(FULL, myla, 2 * qd + half);
            if (ml != N_ITEMS) acc += c1 * v * v - 2.f * v;
        }
        {
            // tail labels 96..99: lanes 0..3 load, broadcast via shfl
            int t = lab[96 + (lane & 3)];
            int lA = __shfl_sync(FULL, t, half);        // label 96+half
            int lB = __shfl_sync(FULL, t, 2 + half);    // label 98+half
            float4 vA = iab[lA * 48];
            float4 vB = iab[lB * 48];
            float pA = vA.x * w4.x + vA.y * w4.y + vA.z * w4.z + vA.w * w4.w;
            float pB = vB.x * w4.x + vB.y * w4.y + vB.z * w4.z + vB.w * w4.w;
#pragma unroll
            for (int o = 8; o >= 1; o >>= 1) {
                pA += __shfl_xor_sync(FULL, pA, o);
                pB += __shfl_xor_sync(FULL, pB, o);
            }
            if (qd == 0) {
                if (lA != N_ITEMS) acc += c1 * pA * pA - 2.f * pA;
                if (lB != N_ITEMS) acc += c1 * pB * pB - 2.f * pB;
            }
        }
#pragma unroll
        for (int o = 16; o >= 1; o >>= 1)
            acc += __shfl_xor_sync(FULL, acc, o);

        if (lane == 0) wsum[warp] = acc;
        __syncthreads();
        if (tid == 0) {
            float s = 0.f;
#pragma unroll
            for (int w = 0; w < 8; w++) s += wsum[w];
            atomicAdd(&g_pos[rel], s);
        }
    }
}

// ---------------------------------------------------------------------------
// Gii holds only b<=c (upper); Gui is full. Off-diagonal weighted x2.
// Re-zeros all accumulators after reading (graph-replay safe).
__global__ void final_kernel(const float* __restrict__ r0,
                             const float* __restrict__ r1,
                             const float* __restrict__ r2,
                             float* __restrict__ out, int out_size)
{
    __shared__ float s1[256], s2[256];
    const int tid = threadIdx.x;
    const float coef[3] = {0.16666f, 0.66666f, 0.16666f};

    float lsum = 0.f, tsum = 0.f;
    for (int idx = tid; idx < NREL * 4096; idx += 256) {
        float gii = g_Gii[idx];
        float gui = g_Gui[idx];
        g_Gii[idx] = 0.f;
        g_Gui[idx] = 0.f;
        int rel = idx >> 12;
        int rem = idx & 4095;
        int b = rem >> 6, cc = rem & 63;
        if (b <= cc) {
            if (b == cc) tsum += gii + gui;
            const float* rr = (rel == 0 ? r0 : rel == 1 ? r1 : r2);
            float m = (b == cc) ? 1.f : 2.f;
            lsum += coef[rel] * 0.1f * m * gii * gui * rr[b] * rr[cc];
        }
    }
    s1[tid] = lsum;
    s2[tid] = tsum;
    __syncthreads();
    for (int s = 128; s > 0; s >>= 1) {
        if (tid < s) { s1[tid] += s1[tid + s]; s2[tid] += s2[tid + s]; }
        __syncthreads();
    }
    if (tid == 0) {
        float loss = s1[0];
#pragma unroll
        for (int r = 0; r < NREL; r++) { loss += coef[r] * g_pos[r]; g_pos[r] = 0.f; }
        out[0] = loss;
        if (out_size > 1) out[1] = 0.01f * 0.5f * s2[0];
    }
}

__global__ void dummy_kernel() {}

// ---------------------------------------------------------------------------
extern "C" void kernel_launch(void* const* d_in, const int* in_sizes, int n_in,
                              void* d_out, int out_size) {
    const int* input_u = (const int*)d_in[0];
    const int* lab0 = (const int*)d_in[1];
    const int* lab1 = (const int*)d_in[2];
    const int* lab2 = (const int*)d_in[3];
    const float* ua = (const float*)d_in[4];
    const float* ia = (const float*)d_in[5];
    const float* r0 = (const float*)d_in[6];
    const float* r1 = (const float*)d_in[7];
    const float* r2 = (const float*)d_in[8];

    cudaFuncSetAttribute(main_kernel, cudaFuncAttributeMaxDynamicSharedMemorySize,
                         DYN_BYTES);

    main_kernel<<<GRID_TOTAL, 256, DYN_BYTES>>>(input_u, lab0, lab1, lab2,
                                                ua, ia, r0, r1, r2);
    final_kernel<<<1, 256>>>(r0, r1, r2, (float*)d_out, out_size);
    dummy_kernel<<<1, 32>>>();   // pads launch stream so ncu -s 5 lands on main_kernel
}